// round 15
// baseline (speedup 1.0000x reference)
#include <cuda_runtime.h>
#include <cuda_fp16.h>
#include <cstdint>

#define SEQ    2048
#define BATCH  2
#define NH     16
#define QKVLD  3072
#define STAGES 3
#define STAGE_BYTES 32768
#define GEMM_SMEM (STAGES * STAGE_BYTES + 1024)
#define NSTG   2
#define ATT_SMEM  (8192 + NSTG * 16384 + 1024)

// ---------------- scratch (static device globals; no allocation) -------------
__device__ __half  g_wqkvh[1024u * 3072u];   // [K=1024, N=3072] row-major
__device__ __half  g_xh   [4096u * 1024u];
__device__ __half  g_qkvh [4096u * 3072u];
__device__ __half  g_oh   [4096u * 1024u];
__device__ __half  g_woh  [1024u * 1024u];   // [K,N] native
__device__ float   g_pp   [2u * 4096u * 1024u];  // split-K partials (2 planes)
__device__ float   g_x1   [4096u * 1024u];
__device__ __half  g_x1h  [4096u * 1024u];
__device__ __half  g_w1h  [1024u * 4096u];   // [K,N] native
__device__ __half  g_hh   [4096u * 4096u];
__device__ __half  g_w2h  [4096u * 1024u];   // [K,N] native

// ---------------- PTX helpers --------------------------------------------------
__device__ __forceinline__ uint32_t smem_u32(const void* p) {
    uint32_t a;
    asm("{ .reg .u64 t; cvta.to.shared.u64 t, %1; cvt.u32.u64 %0, t; }" : "=r"(a) : "l"(p));
    return a;
}
__device__ __forceinline__ void cp16(uint32_t s, const void* g) {
    asm volatile("cp.async.cg.shared.global [%0], [%1], 16;" :: "r"(s), "l"(g));
}
#define CP_COMMIT()  asm volatile("cp.async.commit_group;" ::: "memory")
#define CP_WAIT(n)   asm volatile("cp.async.wait_group %0;" :: "n"(n) : "memory")

__device__ __forceinline__ void ldsm4(uint32_t* r, uint32_t addr) {
    asm volatile("ldmatrix.sync.aligned.m8n8.x4.shared.b16 {%0,%1,%2,%3}, [%4];"
                 : "=r"(r[0]), "=r"(r[1]), "=r"(r[2]), "=r"(r[3]) : "r"(addr));
}
__device__ __forceinline__ void ldsm4t(uint32_t* r, uint32_t addr) {
    asm volatile("ldmatrix.sync.aligned.m8n8.x4.trans.shared.b16 {%0,%1,%2,%3}, [%4];"
                 : "=r"(r[0]), "=r"(r[1]), "=r"(r[2]), "=r"(r[3]) : "r"(addr));
}
__device__ __forceinline__ void mma16816(float* d, const uint32_t* a, uint32_t b0, uint32_t b1) {
    asm volatile(
        "mma.sync.aligned.m16n8k16.row.col.f32.f16.f16.f32 "
        "{%0,%1,%2,%3}, {%4,%5,%6,%7}, {%8,%9}, {%0,%1,%2,%3};"
        : "+f"(d[0]), "+f"(d[1]), "+f"(d[2]), "+f"(d[3])
        : "r"(a[0]), "r"(a[1]), "r"(a[2]), "r"(a[3]), "r"(b0), "r"(b1));
}
__device__ __forceinline__ uint32_t pack2h(float a, float b) {
    __half2 p = __floats2half2_rn(a, b);
    return *reinterpret_cast<uint32_t*>(&p);
}

// ---------------- prep: wqkv pack + x convert (critical-path only) -------------
__global__ void prep_small(const float* __restrict__ Wq, const float* __restrict__ Wk,
                           const float* __restrict__ Wv, __half* __restrict__ wqkv,
                           const float* __restrict__ x,  __half* __restrict__ xh)
{
    int blk = blockIdx.x;
    if (blk < 6144) {
        int t  = blk * 256 + threadIdx.x;          // 0 .. 1572863
        int d  = t / (QKVLD / 2);                  // 0..1023 (3072 NOT pow2 -> div)
        int n  = (t - d * (QKVLD / 2)) * 2;        // even n in row
        int w  = n >> 10;
        int h  = (n >> 6) & 15;
        int k  = n & 63;
        const float* src = (w == 0) ? Wq : (w == 1) ? Wk : Wv;
        float2 v = *(const float2*)&src[h * 65536 + d * 64 + k];
        *reinterpret_cast<uint32_t*>(&wqkv[(size_t)d * QKVLD + n]) = pack2h(v.x, v.y);
        return;
    }
    int rel = blk - 6144;                          // 0..2047, x: 4M elems
    size_t idx = ((size_t)rel * 256 + threadIdx.x) * 8;
    float4 a = *(const float4*)&x[idx];
    float4 b = *(const float4*)&x[idx + 4];
    uint4 o;
    o.x = pack2h(a.x, a.y); o.y = pack2h(a.z, a.w);
    o.z = pack2h(b.x, b.y); o.w = pack2h(b.z, b.w);
    *(uint4*)&xh[idx] = o;
}

// ---------------- mma.sync fp16 GEMM: C = A B ---------------------------------
// A [M,K] fp16 row-major, B [K,N] fp16 row-major (native weight layout).
// CTA tile 128x128x64, 128 threads = 4 warps (2m x 2n), warp tile 64x64.
// ksplit==1: normal; gridDim.z==2 may carry fp32->fp16 cvt side-tasks (z=1).
// ksplit==2: blockIdx.z = K-half; writes fp32 partial to outF + z*M*N
//            (deterministic split-K; combine happens in ln_comb).
__device__ __forceinline__ void g_load_stage(uint32_t sb,
    const __half* A, const __half* B, int K, int N, int m0, int n0, int k0, int tid)
{
#pragma unroll
    for (int it = 0; it < 8; it++) {         // A: 128 rows x 8 chunks
        int idx = it * 128 + tid;
        int r = idx >> 3, c = idx & 7;
        uint32_t soff = (uint32_t)(r * 128 + ((c ^ (r & 7)) << 4));
        cp16(sb + soff, A + (size_t)(m0 + r) * K + k0 + c * 8);
    }
#pragma unroll
    for (int it = 0; it < 8; it++) {         // B: 64 k-rows x 16 chunks
        int idx = it * 128 + tid;
        int r = idx >> 4, c = idx & 15;
        uint32_t soff = (uint32_t)((c >> 3) * 8192 + r * 128 + (((c & 7) ^ (r & 7)) << 4));
        cp16(sb + 16384 + soff, B + (size_t)(k0 + r) * N + n0 + c * 8);
    }
}

__global__ __launch_bounds__(128, 2) void gemm_mma(
    const __half* __restrict__ A, const __half* __restrict__ B,
    int M, int N, int K, int ksplit,
    const float* __restrict__ bias, const float* __restrict__ res, int relu,
    float* __restrict__ outF, __half* __restrict__ outH,
    const float* cv0i, __half* cv0o, int n0blk,
    const float* cv1i, __half* cv1o, int n1blk,
    const float* cv2i, __half* cv2o, int n2blk)
{
    const int zsel = blockIdx.z;
    if (ksplit == 1 && zsel == 1) {
        // side-task plane: fp32 -> fp16 convert, 16384 elems per CTA
        int flat = blockIdx.y * gridDim.x + blockIdx.x;
        const float* in; __half* oh;
        if (flat < n0blk)                        { in = cv0i; oh = cv0o; }
        else if (flat < n0blk + n1blk)           { in = cv1i; oh = cv1o; flat -= n0blk; }
        else if (flat < n0blk + n1blk + n2blk)   { in = cv2i; oh = cv2o; flat -= n0blk + n1blk; }
        else return;
        size_t base_e = (size_t)flat * 16384 + threadIdx.x * 8;
#pragma unroll
        for (int i = 0; i < 16; i++) {
            size_t idx = base_e + (size_t)i * 1024;
            float4 a = *(const float4*)&in[idx];
            float4 b = *(const float4*)&in[idx + 4];
            uint4 o;
            o.x = pack2h(a.x, a.y); o.y = pack2h(a.z, a.w);
            o.z = pack2h(b.x, b.y); o.w = pack2h(b.z, b.w);
            *(uint4*)&oh[idx] = o;
        }
        return;
    }

    extern __shared__ char dsm_raw[];
    uint32_t base = (smem_u32(dsm_raw) + 1023) & ~1023u;

    const int tid  = threadIdx.x;
    const int wid  = tid >> 5;          // 0..3
    const int lane = tid & 31;
    const int wm   = wid >> 1;          // 0..1  (64 rows each)
    const int wn   = wid & 1;           // 0..1  (64 cols each)
    const int m0   = blockIdx.y * 128;
    const int n0   = blockIdx.x * 128;
    const int wr   = wm * 64;
    const int wc   = wn * 64;
    const int l15  = lane & 15;
    const int hi16 = lane >> 4;

    const int Keff  = (ksplit == 2) ? (K >> 1) : K;
    const int kbase = (ksplit == 2) ? zsel * Keff : 0;
    float* outFz = (ksplit == 2) ? outF + (size_t)zsel * M * N : outF;

    uint32_t a_addr[4], a_sw[4];
#pragma unroll
    for (int mt = 0; mt < 4; mt++) {
        int r = wr + mt * 16 + l15;
        a_addr[mt] = (uint32_t)(r * 128);
        a_sw[mt]   = (uint32_t)(r & 7);
    }
    const int b3   = (lane >> 3) & 1;
    const int rsel = ((lane >> 4) << 3) + (lane & 7);   // 0..15 row in k-chunk
    const uint32_t b_base = 16384u + (uint32_t)(wn * 8192) + (uint32_t)(rsel * 128);
    uint32_t co_b[4];
#pragma unroll
    for (int jt = 0; jt < 4; jt++)
        co_b[jt] = (uint32_t)(((jt * 2 + b3) ^ (rsel & 7)) << 4);

    float acc[4][8][4];
#pragma unroll
    for (int i = 0; i < 4; i++)
#pragma unroll
        for (int j = 0; j < 8; j++)
#pragma unroll
            for (int q = 0; q < 4; q++) acc[i][j][q] = 0.f;

    const int nK = Keff >> 6;

#pragma unroll
    for (int s = 0; s < STAGES - 1; s++) {
        g_load_stage(base + s * STAGE_BYTES, A, B, K, N, m0, n0, kbase + s * 64, tid);
        CP_COMMIT();
    }

    for (int kt = 0; kt < nK; kt++) {
        CP_WAIT(STAGES - 2);
        __syncthreads();    // also orders reuse of stage (kt+2)%3 == (kt-1)%3

        int ls = kt + STAGES - 1;
        if (ls < nK)
            g_load_stage(base + (ls % STAGES) * STAGE_BYTES, A, B, K, N, m0, n0,
                         kbase + ls * 64, tid);
        CP_COMMIT();

        uint32_t sb = base + (kt % STAGES) * STAGE_BYTES;
#pragma unroll
        for (int kh = 0; kh < 4; kh++) {
            uint32_t ah[4][4];
#pragma unroll
            for (int mt = 0; mt < 4; mt++)
                ldsm4(ah[mt], sb + a_addr[mt] + (((2 * kh + hi16) ^ a_sw[mt]) << 4));
#pragma unroll
            for (int jt = 0; jt < 4; jt++) {   // 1 ldsm4t feeds 8 MMAs
                uint32_t t[4];
                ldsm4t(t, sb + b_base + (uint32_t)(kh * 2048) + co_b[jt]);
#pragma unroll
                for (int mt = 0; mt < 4; mt++) {
                    mma16816(acc[mt][2 * jt],     ah[mt], t[0], t[2]);
                    mma16816(acc[mt][2 * jt + 1], ah[mt], t[1], t[3]);
                }
            }
        }
    }
    __syncthreads();

    const int rq = lane >> 2;
    const int cq = (lane & 3) * 2;
#pragma unroll
    for (int mt = 0; mt < 4; mt++)
#pragma unroll
        for (int half = 0; half < 2; half++) {
            int row = m0 + wr + mt * 16 + rq + half * 8;
            size_t rb = (size_t)row * N;
#pragma unroll
            for (int j = 0; j < 8; j++) {
                int col = n0 + wc + j * 8 + cq;
                float v0 = acc[mt][j][half * 2 + 0];
                float v1 = acc[mt][j][half * 2 + 1];
                if (bias) { v0 += bias[col]; v1 += bias[col + 1]; }
                if (relu) { v0 = fmaxf(v0, 0.f); v1 = fmaxf(v1, 0.f); }
                if (res)  {
                    float2 rr = *(const float2*)&res[rb + col];
                    v0 += rr.x; v1 += rr.y;
                }
                if (outFz) *(float2*)&outFz[rb + col] = make_float2(v0, v1);
                if (outH)  *reinterpret_cast<uint32_t*>(outH + rb + col) = pack2h(v0, v1);
            }
        }
}

// ---------------- HMMA flash attention -----------------------------------------
// 64-row Q tiles, 128 threads (4 warps x 16 q-rows), 2 KV stages, occ 4.
// smem: Q[0,8K); KV stage s at 8K+s*16K: K[0,8K) V[8K,16K).
__device__ __forceinline__ void att_load_kv(uint32_t sb,
    const __half* qkv, size_t tokbase, int h, int kt, int tid)
{
#pragma unroll
    for (int it = 0; it < 4; it++) {
        int idx = it * 128 + tid;       // 0..511 : 64 rows x 8 chunks
        int r = idx >> 3, c = idx & 7;
        uint32_t sw = (uint32_t)(r * 128 + ((c ^ (r & 7)) << 4));
        size_t gk = (tokbase + kt * 64 + r) * QKVLD + 1024 + h * 64 + c * 8;
        cp16(sb        + sw, qkv + gk);
        cp16(sb + 8192 + sw, qkv + gk + 1024);
    }
}

__global__ __launch_bounds__(128, 4) void flash_hmma(
    const __half* __restrict__ qkv, __half* __restrict__ oh)
{
    extern __shared__ char smem_raw[];
    uint32_t base = (smem_u32(smem_raw) + 1023) & ~1023u;
    const uint32_t QH = base;

    const int tid  = threadIdx.x;
    const int wq   = tid >> 5;           // 0..3
    const int lane = tid & 31;
    const int l15  = lane & 15;
    const int hi16 = lane >> 4;
    const int q0   = blockIdx.x * 64;
    const int h    = blockIdx.y;
    const int b    = blockIdx.z;
    const size_t tokbase = (size_t)b * SEQ;

    // Q tile (64 rows) + KV stage 0 in group 0
#pragma unroll
    for (int it = 0; it < 4; it++) {
        int idx = it * 128 + tid;        // 0..511
        int r = idx >> 3, c = idx & 7;
        uint32_t sw = (uint32_t)(r * 128 + ((c ^ (r & 7)) << 4));
        cp16(QH + sw, qkv + (tokbase + q0 + r) * QKVLD + h * 64 + c * 8);
    }
    att_load_kv(base + 8192, qkv, tokbase, h, 0, tid);
    CP_COMMIT();

    float m2[2] = {-1e30f, -1e30f};
    float l2[2] = {0.f, 0.f};
    float oa[8][4];
#pragma unroll
    for (int j = 0; j < 8; j++)
#pragma unroll
        for (int q = 0; q < 4; q++) oa[j][q] = 0.f;

    const uint32_t qrow = (uint32_t)((wq * 16 + l15) * 128);
    const uint32_t qsw  = (uint32_t)((wq * 16 + l15) & 7);
    const int rsel = ((lane >> 4) << 3) + (lane & 7);
    const int b3   = (lane >> 3) & 1;

    for (int kt = 0; kt < SEQ / 64; kt++) {
        CP_WAIT(0);
        __syncthreads();
        int ls = kt + 1;
        if (ls < SEQ / 64)
            att_load_kv(base + 8192 + (ls & 1) * 16384, qkv, tokbase, h, ls, tid);
        CP_COMMIT();

        uint32_t sb = base + 8192 + (kt & 1) * 16384;

        // ---- S = Q K^T -------------------------------------------------------
        float sa[8][4];
#pragma unroll
        for (int j = 0; j < 8; j++)
#pragma unroll
            for (int q = 0; q < 4; q++) sa[j][q] = 0.f;

#pragma unroll
        for (int kc = 0; kc < 4; kc++) {
            uint32_t co_a = (uint32_t)(((2 * kc + hi16) ^ qsw) << 4);
            uint32_t ah[4];
            ldsm4(ah, QH + qrow + co_a);
#pragma unroll
            for (int nt = 0; nt < 4; nt++) {   // consume K frags immediately
                int r = nt * 16 + l15;
                uint32_t co = (uint32_t)(((2 * kc + hi16) ^ (r & 7)) << 4);
                uint32_t t[4];
                ldsm4(t, sb + r * 128 + co);
                mma16816(sa[2 * nt],     ah, t[0], t[2]);
                mma16816(sa[2 * nt + 1], ah, t[1], t[3]);
            }
        }

        // ---- online softmax ---------------------------------------------------
#pragma unroll
        for (int half = 0; half < 2; half++) {
            float mx = -1e30f;
#pragma unroll
            for (int j = 0; j < 8; j++) {
                sa[j][2 * half]     *= 0.125f;
                sa[j][2 * half + 1] *= 0.125f;
                mx = fmaxf(mx, fmaxf(sa[j][2 * half], sa[j][2 * half + 1]));
            }
            mx = fmaxf(mx, __shfl_xor_sync(0xffffffffu, mx, 1));
            mx = fmaxf(mx, __shfl_xor_sync(0xffffffffu, mx, 2));
            float nm    = fmaxf(m2[half], mx);
            float alpha = __expf(m2[half] - nm);
            float rs = 0.f;
#pragma unroll
            for (int j = 0; j < 8; j++) {
                sa[j][2 * half]     = __expf(sa[j][2 * half]     - nm);
                sa[j][2 * half + 1] = __expf(sa[j][2 * half + 1] - nm);
                rs += sa[j][2 * half] + sa[j][2 * half + 1];
            }
            rs += __shfl_xor_sync(0xffffffffu, rs, 1);
            rs += __shfl_xor_sync(0xffffffffu, rs, 2);
            l2[half] = l2[half] * alpha + rs;
            m2[half] = nm;
#pragma unroll
            for (int j = 0; j < 8; j++) {
                oa[j][2 * half]     *= alpha;
                oa[j][2 * half + 1] *= alpha;
            }
        }

        // ---- O += P V; P frags built per-kc, V frags consumed immediately -------
#pragma unroll
        for (int kc = 0; kc < 4; kc++) {
            uint32_t ph[4];
            int j0 = 2 * kc, j1 = 2 * kc + 1;
            ph[0] = pack2h(sa[j0][0], sa[j0][1]);
            ph[1] = pack2h(sa[j0][2], sa[j0][3]);
            ph[2] = pack2h(sa[j1][0], sa[j1][1]);
            ph[3] = pack2h(sa[j1][2], sa[j1][3]);
            int rowt = kc * 16 + rsel;
#pragma unroll
            for (int jt = 0; jt < 4; jt++) {
                int c8 = jt * 2 + b3;
                uint32_t ad = sb + 8192 + rowt * 128 + (uint32_t)((c8 ^ (rowt & 7)) << 4);
                uint32_t t[4];
                ldsm4t(t, ad);
                mma16816(oa[2 * jt],     ph, t[0], t[2]);
                mma16816(oa[2 * jt + 1], ph, t[1], t[3]);
            }
        }
    }

    // ---- epilogue ---------------------------------------------------------------
    float inv0 = 1.f / l2[0];
    float inv1 = 1.f / l2[1];
    int r0 = q0 + wq * 16 + (lane >> 2);
#pragma unroll
    for (int j = 0; j < 8; j++) {
        int col = h * 64 + j * 8 + (lane & 3) * 2;
        size_t g0 = (tokbase + r0) * 1024 + col;
        size_t g1 = (tokbase + r0 + 8) * 1024 + col;
        *reinterpret_cast<uint32_t*>(oh + g0) = pack2h(oa[j][0] * inv0, oa[j][1] * inv0);
        *reinterpret_cast<uint32_t*>(oh + g1) = pack2h(oa[j][2] * inv1, oa[j][3] * inv1);
    }
}

// ---------------- layernorm with split-K combine --------------------------------
// v = in0 + in1 + res (+ bias); LN(v) -> outF (fp32, optional) + outH (fp16, opt)
__global__ __launch_bounds__(256) void ln_comb(const float* __restrict__ in0,
                                               const float* __restrict__ in1,
                                               const float* __restrict__ res,
                                               const float* __restrict__ bias,
                                               const float* __restrict__ gamma,
                                               const float* __restrict__ beta,
                                               float* __restrict__ outF,
                                               __half* __restrict__ outH)
{
    const int row = blockIdx.x, tid = threadIdx.x;
    size_t idx = (size_t)row * 1024 + tid * 4;
    float4 v  = *(const float4*)&in0[idx];
    float4 p1 = *(const float4*)&in1[idx];
    float4 rr = *(const float4*)&res[idx];
    v.x = (v.x + p1.x) + rr.x;
    v.y = (v.y + p1.y) + rr.y;
    v.z = (v.z + p1.z) + rr.z;
    v.w = (v.w + p1.w) + rr.w;
    if (bias) {
        float4 bb = *(const float4*)&bias[tid * 4];
        v.x += bb.x; v.y += bb.y; v.z += bb.z; v.w += bb.w;
    }
    float s  = v.x + v.y + v.z + v.w;
    float ss = v.x * v.x + v.y * v.y + v.z * v.z + v.w * v.w;
#pragma unroll
    for (int off = 16; off > 0; off >>= 1) {
        s  += __shfl_xor_sync(0xffffffffu, s,  off);
        ss += __shfl_xor_sync(0xffffffffu, ss, off);
    }
    __shared__ float sb[8], ssb[8];
    __shared__ float smu, sinv;
    if ((tid & 31) == 0) { sb[tid >> 5] = s; ssb[tid >> 5] = ss; }
    __syncthreads();
    if (tid == 0) {
        float S = 0.f, SS = 0.f;
#pragma unroll
        for (int i = 0; i < 8; i++) { S += sb[i]; SS += ssb[i]; }
        float mu  = S * (1.f / 1024.f);
        float var = SS * (1.f / 1024.f) - mu * mu;
        smu = mu; sinv = rsqrtf(var + 1e-5f);
    }
    __syncthreads();
    float mu = smu, inv = sinv;
    float4 g = *(const float4*)(gamma + tid * 4);
    float4 b = *(const float4*)(beta  + tid * 4);
    float4 o;
    o.x = (v.x - mu) * inv * g.x + b.x;
    o.y = (v.y - mu) * inv * g.y + b.y;
    o.z = (v.z - mu) * inv * g.z + b.z;
    o.w = (v.w - mu) * inv * g.w + b.w;
    if (outF) *(float4*)&outF[idx] = o;
    if (outH) {
        *reinterpret_cast<uint32_t*>(outH + idx)     = pack2h(o.x, o.y);
        *reinterpret_cast<uint32_t*>(outH + idx + 2) = pack2h(o.z, o.w);
    }
}

// ---------------- launch ----------------------------------------------------------
extern "C" void kernel_launch(void* const* d_in, const int* in_sizes, int n_in,
                              void* d_out, int out_size)
{
    const float* x     = (const float*)d_in[0];
    const float* Wq    = (const float*)d_in[1];
    const float* Wk    = (const float*)d_in[2];
    const float* Wv    = (const float*)d_in[3];
    const float* Wo    = (const float*)d_in[4];
    const float* ln1_g = (const float*)d_in[5];
    const float* ln1_b = (const float*)d_in[6];
    const float* W1    = (const float*)d_in[7];
    const float* b1    = (const float*)d_in[8];
    const float* W2    = (const float*)d_in[9];
    const float* b2    = (const float*)d_in[10];
    const float* ln2_g = (const float*)d_in[11];
    const float* ln2_b = (const float*)d_in[12];
    float* out = (float*)d_out;

    cudaFuncSetAttribute(gemm_mma,   cudaFuncAttributeMaxDynamicSharedMemorySize, GEMM_SMEM);
    cudaFuncSetAttribute(flash_hmma, cudaFuncAttributeMaxDynamicSharedMemorySize, ATT_SMEM);

    float *pp, *x1;
    __half *wqkvh, *xh, *qkvh, *oh, *woh, *x1h, *w1h, *hh, *w2h;
    cudaGetSymbolAddress((void**)&pp,    g_pp);
    cudaGetSymbolAddress((void**)&x1,    g_x1);
    cudaGetSymbolAddress((void**)&wqkvh, g_wqkvh);
    cudaGetSymbolAddress((void**)&xh,    g_xh);
    cudaGetSymbolAddress((void**)&qkvh,  g_qkvh);
    cudaGetSymbolAddress((void**)&oh,    g_oh);
    cudaGetSymbolAddress((void**)&woh,   g_woh);
    cudaGetSymbolAddress((void**)&x1h,   g_x1h);
    cudaGetSymbolAddress((void**)&w1h,   g_w1h);
    cudaGetSymbolAddress((void**)&hh,    g_hh);
    cudaGetSymbolAddress((void**)&w2h,   g_w2h);

    // 0. critical-path prep only (wqkv pack + x convert)
    prep_small<<<8192, 256>>>(Wq, Wk, Wv, wqkvh, x, xh);

    // 1. QKV projection -> qkv fp16; z=1 plane converts Wo/W1/W2 in the tail
    gemm_mma<<<dim3(24, 32, 2), 128, GEMM_SMEM>>>(xh, wqkvh, 4096, 3072, 1024, 1,
                                                  nullptr, nullptr, 0, nullptr, qkvh,
                                                  Wo, woh, 64, W1, w1h, 256, W2, w2h, 256);
    // 2. flash attention -> o fp16 (64-row Q tiles, occ4)
    flash_hmma<<<dim3(32, NH, BATCH), 128, ATT_SMEM>>>(qkvh, oh);
    // 3. output projection, split-K2 -> fp32 partials pp[0], pp[1]
    gemm_mma<<<dim3(8, 32, 2), 128, GEMM_SMEM>>>(oh, woh, 4096, 1024, 1024, 2,
                                                 nullptr, nullptr, 0, pp, nullptr,
                                                 nullptr, nullptr, 0, nullptr, nullptr, 0,
                                                 nullptr, nullptr, 0);
    // 4. LN1 over (pp0 + pp1 + x) -> x1 fp32 + x1h fp16
    ln_comb<<<4096, 256>>>(pp, pp + 4096u * 1024u, x, nullptr, ln1_g, ln1_b, x1, x1h);
    // 5. FFN up + bias + relu -> h fp16
    gemm_mma<<<dim3(32, 32, 1), 128, GEMM_SMEM>>>(x1h, w1h, 4096, 4096, 1024, 1,
                                                  b1, nullptr, 1, nullptr, hh,
                                                  nullptr, nullptr, 0, nullptr, nullptr, 0,
                                                  nullptr, nullptr, 0);
    // 6. FFN down, split-K2 -> fp32 partials pp[0], pp[1]
    gemm_mma<<<dim3(8, 32, 2), 128, GEMM_SMEM>>>(hh, w2h, 4096, 1024, 4096, 2,
                                                 nullptr, nullptr, 0, pp, nullptr,
                                                 nullptr, nullptr, 0, nullptr, nullptr, 0,
                                                 nullptr, nullptr, 0);
    // 7. LN2 over (pp0 + pp1 + x1 + b2) -> out
    ln_comb<<<4096, 256>>>(pp, pp + 4096u * 1024u, x1, b2, ln2_g, ln2_b, out, nullptr);
}

// round 16
// speedup vs baseline: 1.0304x; 1.0304x over previous
#include <cuda_runtime.h>
#include <cuda_fp16.h>
#include <cstdint>

#define SEQ    2048
#define BATCH  2
#define NH     16
#define QKVLD  3072
#define STAGES 3
#define STAGE_BYTES 32768
#define GEMM_SMEM (STAGES * STAGE_BYTES + 1024)
#define NSTG   2
#define ATT_SMEM  (8192 + NSTG * 16384 + 1024)

// ---------------- scratch (static device globals; no allocation) -------------
__device__ __half  g_wqkvh[1024u * 3072u];   // [K=1024, N=3072] row-major
__device__ __half  g_xh   [4096u * 1024u];
__device__ __half  g_qkvh [4096u * 3072u];
__device__ __half  g_oh   [4096u * 1024u];
__device__ __half  g_woh  [1024u * 1024u];   // [K,N] native
__device__ __half  g_t1h  [4096u * 1024u];   // attn_out + x (fp16)
__device__ __half  g_x1h  [4096u * 1024u];   // LN1 out (fp16 only)
__device__ __half  g_w1h  [1024u * 4096u];   // [K,N] native
__device__ __half  g_hh   [4096u * 4096u];
__device__ __half  g_w2h  [4096u * 1024u];   // [K,N] native
__device__ float   g_t2   [4096u * 1024u];   // ffn + x1 (fp32, final LN input)

// ---------------- PTX helpers --------------------------------------------------
__device__ __forceinline__ uint32_t smem_u32(const void* p) {
    uint32_t a;
    asm("{ .reg .u64 t; cvta.to.shared.u64 t, %1; cvt.u32.u64 %0, t; }" : "=r"(a) : "l"(p));
    return a;
}
__device__ __forceinline__ void cp16(uint32_t s, const void* g) {
    asm volatile("cp.async.cg.shared.global [%0], [%1], 16;" :: "r"(s), "l"(g));
}
#define CP_COMMIT()  asm volatile("cp.async.commit_group;" ::: "memory")
#define CP_WAIT(n)   asm volatile("cp.async.wait_group %0;" :: "n"(n) : "memory")

__device__ __forceinline__ void ldsm4(uint32_t* r, uint32_t addr) {
    asm volatile("ldmatrix.sync.aligned.m8n8.x4.shared.b16 {%0,%1,%2,%3}, [%4];"
                 : "=r"(r[0]), "=r"(r[1]), "=r"(r[2]), "=r"(r[3]) : "r"(addr));
}
__device__ __forceinline__ void ldsm4t(uint32_t* r, uint32_t addr) {
    asm volatile("ldmatrix.sync.aligned.m8n8.x4.trans.shared.b16 {%0,%1,%2,%3}, [%4];"
                 : "=r"(r[0]), "=r"(r[1]), "=r"(r[2]), "=r"(r[3]) : "r"(addr));
}
__device__ __forceinline__ void mma16816(float* d, const uint32_t* a, uint32_t b0, uint32_t b1) {
    asm volatile(
        "mma.sync.aligned.m16n8k16.row.col.f32.f16.f16.f32 "
        "{%0,%1,%2,%3}, {%4,%5,%6,%7}, {%8,%9}, {%0,%1,%2,%3};"
        : "+f"(d[0]), "+f"(d[1]), "+f"(d[2]), "+f"(d[3])
        : "r"(a[0]), "r"(a[1]), "r"(a[2]), "r"(a[3]), "r"(b0), "r"(b1));
}
__device__ __forceinline__ uint32_t pack2h(float a, float b) {
    __half2 p = __floats2half2_rn(a, b);
    return *reinterpret_cast<uint32_t*>(&p);
}

// ---------------- prep: wqkv pack + x convert (critical-path only) -------------
__global__ void prep_small(const float* __restrict__ Wq, const float* __restrict__ Wk,
                           const float* __restrict__ Wv, __half* __restrict__ wqkv,
                           const float* __restrict__ x,  __half* __restrict__ xh)
{
    int blk = blockIdx.x;
    if (blk < 6144) {
        int t  = blk * 256 + threadIdx.x;          // 0 .. 1572863
        int d  = t / (QKVLD / 2);                  // 0..1023 (3072 NOT pow2 -> div)
        int n  = (t - d * (QKVLD / 2)) * 2;        // even n in row
        int w  = n >> 10;
        int h  = (n >> 6) & 15;
        int k  = n & 63;
        const float* src = (w == 0) ? Wq : (w == 1) ? Wk : Wv;
        float2 v = *(const float2*)&src[h * 65536 + d * 64 + k];
        *reinterpret_cast<uint32_t*>(&wqkv[(size_t)d * QKVLD + n]) = pack2h(v.x, v.y);
        return;
    }
    int rel = blk - 6144;                          // 0..2047, x: 4M elems
    size_t idx = ((size_t)rel * 256 + threadIdx.x) * 8;
    float4 a = *(const float4*)&x[idx];
    float4 b = *(const float4*)&x[idx + 4];
    uint4 o;
    o.x = pack2h(a.x, a.y); o.y = pack2h(a.z, a.w);
    o.z = pack2h(b.x, b.y); o.w = pack2h(b.z, b.w);
    *(uint4*)&xh[idx] = o;
}

// ---------------- mma.sync fp16 GEMM: C = A B ---------------------------------
// A [M,K] fp16 row-major, B [K,N] fp16 row-major (native weight layout).
// CTA tile 128x128x64, 128 threads = 4 warps (2m x 2n), warp tile 64x64.
// gridDim.z==2 carries fp32->fp16 weight-convert side-tasks in the z=1 plane.
__device__ __forceinline__ void g_load_stage(uint32_t sb,
    const __half* A, const __half* B, int K, int N, int m0, int n0, int k0, int tid)
{
#pragma unroll
    for (int it = 0; it < 8; it++) {         // A: 128 rows x 8 chunks
        int idx = it * 128 + tid;
        int r = idx >> 3, c = idx & 7;
        uint32_t soff = (uint32_t)(r * 128 + ((c ^ (r & 7)) << 4));
        cp16(sb + soff, A + (size_t)(m0 + r) * K + k0 + c * 8);
    }
#pragma unroll
    for (int it = 0; it < 8; it++) {         // B: 64 k-rows x 16 chunks
        int idx = it * 128 + tid;
        int r = idx >> 4, c = idx & 15;
        uint32_t soff = (uint32_t)((c >> 3) * 8192 + r * 128 + (((c & 7) ^ (r & 7)) << 4));
        cp16(sb + 16384 + soff, B + (size_t)(k0 + r) * N + n0 + c * 8);
    }
}

__global__ __launch_bounds__(128, 2) void gemm_mma(
    const __half* __restrict__ A, const __half* __restrict__ B,
    int M, int N, int K,
    const float* __restrict__ bias, const float* __restrict__ res,
    const __half* __restrict__ resH, int relu,
    float* __restrict__ outF, __half* __restrict__ outH,
    const float* cv0i, __half* cv0o, int n0blk,
    const float* cv1i, __half* cv1o, int n1blk,
    const float* cv2i, __half* cv2o, int n2blk)
{
    if (blockIdx.z == 1) {
        // side-task plane: fp32 -> fp16 convert, 16384 elems per CTA
        int flat = blockIdx.y * gridDim.x + blockIdx.x;
        const float* in; __half* oh;
        if (flat < n0blk)                        { in = cv0i; oh = cv0o; }
        else if (flat < n0blk + n1blk)           { in = cv1i; oh = cv1o; flat -= n0blk; }
        else if (flat < n0blk + n1blk + n2blk)   { in = cv2i; oh = cv2o; flat -= n0blk + n1blk; }
        else return;
        size_t base_e = (size_t)flat * 16384 + threadIdx.x * 8;
#pragma unroll
        for (int i = 0; i < 16; i++) {
            size_t idx = base_e + (size_t)i * 1024;
            float4 a = *(const float4*)&in[idx];
            float4 b = *(const float4*)&in[idx + 4];
            uint4 o;
            o.x = pack2h(a.x, a.y); o.y = pack2h(a.z, a.w);
            o.z = pack2h(b.x, b.y); o.w = pack2h(b.z, b.w);
            *(uint4*)&oh[idx] = o;
        }
        return;
    }

    extern __shared__ char dsm_raw[];
    uint32_t base = (smem_u32(dsm_raw) + 1023) & ~1023u;

    const int tid  = threadIdx.x;
    const int wid  = tid >> 5;          // 0..3
    const int lane = tid & 31;
    const int wm   = wid >> 1;          // 0..1  (64 rows each)
    const int wn   = wid & 1;           // 0..1  (64 cols each)
    const int m0   = blockIdx.y * 128;
    const int n0   = blockIdx.x * 128;
    const int wr   = wm * 64;
    const int wc   = wn * 64;
    const int l15  = lane & 15;
    const int hi16 = lane >> 4;

    uint32_t a_addr[4], a_sw[4];
#pragma unroll
    for (int mt = 0; mt < 4; mt++) {
        int r = wr + mt * 16 + l15;
        a_addr[mt] = (uint32_t)(r * 128);
        a_sw[mt]   = (uint32_t)(r & 7);
    }
    const int b3   = (lane >> 3) & 1;
    const int rsel = ((lane >> 4) << 3) + (lane & 7);   // 0..15 row in k-chunk
    const uint32_t b_base = 16384u + (uint32_t)(wn * 8192) + (uint32_t)(rsel * 128);
    uint32_t co_b[4];
#pragma unroll
    for (int jt = 0; jt < 4; jt++)
        co_b[jt] = (uint32_t)(((jt * 2 + b3) ^ (rsel & 7)) << 4);

    float acc[4][8][4];
#pragma unroll
    for (int i = 0; i < 4; i++)
#pragma unroll
        for (int j = 0; j < 8; j++)
#pragma unroll
            for (int q = 0; q < 4; q++) acc[i][j][q] = 0.f;

    const int nK = K >> 6;

#pragma unroll
    for (int s = 0; s < STAGES - 1; s++) {
        g_load_stage(base + s * STAGE_BYTES, A, B, K, N, m0, n0, s * 64, tid);
        CP_COMMIT();
    }

    for (int kt = 0; kt < nK; kt++) {
        CP_WAIT(STAGES - 2);
        __syncthreads();    // also orders reuse of stage (kt+2)%3 == (kt-1)%3

        int ls = kt + STAGES - 1;
        if (ls < nK)
            g_load_stage(base + (ls % STAGES) * STAGE_BYTES, A, B, K, N, m0, n0, ls * 64, tid);
        CP_COMMIT();

        uint32_t sb = base + (kt % STAGES) * STAGE_BYTES;
#pragma unroll
        for (int kh = 0; kh < 4; kh++) {
            uint32_t ah[4][4];
#pragma unroll
            for (int mt = 0; mt < 4; mt++)
                ldsm4(ah[mt], sb + a_addr[mt] + (((2 * kh + hi16) ^ a_sw[mt]) << 4));
#pragma unroll
            for (int jt = 0; jt < 4; jt++) {   // 1 ldsm4t feeds 8 MMAs
                uint32_t t[4];
                ldsm4t(t, sb + b_base + (uint32_t)(kh * 2048) + co_b[jt]);
#pragma unroll
                for (int mt = 0; mt < 4; mt++) {
                    mma16816(acc[mt][2 * jt],     ah[mt], t[0], t[2]);
                    mma16816(acc[mt][2 * jt + 1], ah[mt], t[1], t[3]);
                }
            }
        }
    }
    __syncthreads();

    const int rq = lane >> 2;
    const int cq = (lane & 3) * 2;
#pragma unroll
    for (int mt = 0; mt < 4; mt++)
#pragma unroll
        for (int half = 0; half < 2; half++) {
            int row = m0 + wr + mt * 16 + rq + half * 8;
            size_t rb = (size_t)row * N;
#pragma unroll
            for (int j = 0; j < 8; j++) {
                int col = n0 + wc + j * 8 + cq;
                float v0 = acc[mt][j][half * 2 + 0];
                float v1 = acc[mt][j][half * 2 + 1];
                if (bias) { v0 += bias[col]; v1 += bias[col + 1]; }
                if (relu) { v0 = fmaxf(v0, 0.f); v1 = fmaxf(v1, 0.f); }
                if (res)  {
                    float2 rr = *(const float2*)&res[rb + col];
                    v0 += rr.x; v1 += rr.y;
                }
                if (resH) {
                    __half2 rh = *reinterpret_cast<const __half2*>(resH + rb + col);
                    v0 += __half2float(rh.x); v1 += __half2float(rh.y);
                }
                if (outF) *(float2*)&outF[rb + col] = make_float2(v0, v1);
                if (outH) *reinterpret_cast<uint32_t*>(outH + rb + col) = pack2h(v0, v1);
            }
        }
}

// ---------------- HMMA flash attention -----------------------------------------
// 64-row Q tiles, 128 threads (4 warps x 16 q-rows), 2 KV stages, occ 4.
// smem: Q[0,8K); KV stage s at 8K+s*16K: K[0,8K) V[8K,16K).
__device__ __forceinline__ void att_load_kv(uint32_t sb,
    const __half* qkv, size_t tokbase, int h, int kt, int tid)
{
#pragma unroll
    for (int it = 0; it < 4; it++) {
        int idx = it * 128 + tid;       // 0..511 : 64 rows x 8 chunks
        int r = idx >> 3, c = idx & 7;
        uint32_t sw = (uint32_t)(r * 128 + ((c ^ (r & 7)) << 4));
        size_t gk = (tokbase + kt * 64 + r) * QKVLD + 1024 + h * 64 + c * 8;
        cp16(sb        + sw, qkv + gk);
        cp16(sb + 8192 + sw, qkv + gk + 1024);
    }
}

__global__ __launch_bounds__(128, 4) void flash_hmma(
    const __half* __restrict__ qkv, __half* __restrict__ oh)
{
    extern __shared__ char smem_raw[];
    uint32_t base = (smem_u32(smem_raw) + 1023) & ~1023u;
    const uint32_t QH = base;

    const int tid  = threadIdx.x;
    const int wq   = tid >> 5;           // 0..3
    const int lane = tid & 31;
    const int l15  = lane & 15;
    const int hi16 = lane >> 4;
    const int q0   = blockIdx.x * 64;
    const int h    = blockIdx.y;
    const int b    = blockIdx.z;
    const size_t tokbase = (size_t)b * SEQ;

    // Q tile (64 rows) + KV stage 0 in group 0
#pragma unroll
    for (int it = 0; it < 4; it++) {
        int idx = it * 128 + tid;        // 0..511
        int r = idx >> 3, c = idx & 7;
        uint32_t sw = (uint32_t)(r * 128 + ((c ^ (r & 7)) << 4));
        cp16(QH + sw, qkv + (tokbase + q0 + r) * QKVLD + h * 64 + c * 8);
    }
    att_load_kv(base + 8192, qkv, tokbase, h, 0, tid);
    CP_COMMIT();

    float m2[2] = {-1e30f, -1e30f};
    float l2[2] = {0.f, 0.f};
    float oa[8][4];
#pragma unroll
    for (int j = 0; j < 8; j++)
#pragma unroll
        for (int q = 0; q < 4; q++) oa[j][q] = 0.f;

    const uint32_t qrow = (uint32_t)((wq * 16 + l15) * 128);
    const uint32_t qsw  = (uint32_t)((wq * 16 + l15) & 7);
    const int rsel = ((lane >> 4) << 3) + (lane & 7);
    const int b3   = (lane >> 3) & 1;

    for (int kt = 0; kt < SEQ / 64; kt++) {
        CP_WAIT(0);
        __syncthreads();
        int ls = kt + 1;
        if (ls < SEQ / 64)
            att_load_kv(base + 8192 + (ls & 1) * 16384, qkv, tokbase, h, ls, tid);
        CP_COMMIT();

        uint32_t sb = base + 8192 + (kt & 1) * 16384;

        // ---- S = Q K^T -------------------------------------------------------
        float sa[8][4];
#pragma unroll
        for (int j = 0; j < 8; j++)
#pragma unroll
            for (int q = 0; q < 4; q++) sa[j][q] = 0.f;

#pragma unroll
        for (int kc = 0; kc < 4; kc++) {
            uint32_t co_a = (uint32_t)(((2 * kc + hi16) ^ qsw) << 4);
            uint32_t ah[4];
            ldsm4(ah, QH + qrow + co_a);
#pragma unroll
            for (int nt = 0; nt < 4; nt++) {   // consume K frags immediately
                int r = nt * 16 + l15;
                uint32_t co = (uint32_t)(((2 * kc + hi16) ^ (r & 7)) << 4);
                uint32_t t[4];
                ldsm4(t, sb + r * 128 + co);
                mma16816(sa[2 * nt],     ah, t[0], t[2]);
                mma16816(sa[2 * nt + 1], ah, t[1], t[3]);
            }
        }

        // ---- online softmax ---------------------------------------------------
#pragma unroll
        for (int half = 0; half < 2; half++) {
            float mx = -1e30f;
#pragma unroll
            for (int j = 0; j < 8; j++) {
                sa[j][2 * half]     *= 0.125f;
                sa[j][2 * half + 1] *= 0.125f;
                mx = fmaxf(mx, fmaxf(sa[j][2 * half], sa[j][2 * half + 1]));
            }
            mx = fmaxf(mx, __shfl_xor_sync(0xffffffffu, mx, 1));
            mx = fmaxf(mx, __shfl_xor_sync(0xffffffffu, mx, 2));
            float nm    = fmaxf(m2[half], mx);
            float alpha = __expf(m2[half] - nm);
            float rs = 0.f;
#pragma unroll
            for (int j = 0; j < 8; j++) {
                sa[j][2 * half]     = __expf(sa[j][2 * half]     - nm);
                sa[j][2 * half + 1] = __expf(sa[j][2 * half + 1] - nm);
                rs += sa[j][2 * half] + sa[j][2 * half + 1];
            }
            rs += __shfl_xor_sync(0xffffffffu, rs, 1);
            rs += __shfl_xor_sync(0xffffffffu, rs, 2);
            l2[half] = l2[half] * alpha + rs;
            m2[half] = nm;
#pragma unroll
            for (int j = 0; j < 8; j++) {
                oa[j][2 * half]     *= alpha;
                oa[j][2 * half + 1] *= alpha;
            }
        }

        // ---- O += P V; P frags built per-kc, V frags consumed immediately -------
#pragma unroll
        for (int kc = 0; kc < 4; kc++) {
            uint32_t ph[4];
            int j0 = 2 * kc, j1 = 2 * kc + 1;
            ph[0] = pack2h(sa[j0][0], sa[j0][1]);
            ph[1] = pack2h(sa[j0][2], sa[j0][3]);
            ph[2] = pack2h(sa[j1][0], sa[j1][1]);
            ph[3] = pack2h(sa[j1][2], sa[j1][3]);
            int rowt = kc * 16 + rsel;
#pragma unroll
            for (int jt = 0; jt < 4; jt++) {
                int c8 = jt * 2 + b3;
                uint32_t ad = sb + 8192 + rowt * 128 + (uint32_t)((c8 ^ (rowt & 7)) << 4);
                uint32_t t[4];
                ldsm4t(t, ad);
                mma16816(oa[2 * jt],     ph, t[0], t[2]);
                mma16816(oa[2 * jt + 1], ph, t[1], t[3]);
            }
        }
    }

    // ---- epilogue ---------------------------------------------------------------
    float inv0 = 1.f / l2[0];
    float inv1 = 1.f / l2[1];
    int r0 = q0 + wq * 16 + (lane >> 2);
#pragma unroll
    for (int j = 0; j < 8; j++) {
        int col = h * 64 + j * 8 + (lane & 3) * 2;
        size_t g0 = (tokbase + r0) * 1024 + col;
        size_t g1 = (tokbase + r0 + 8) * 1024 + col;
        *reinterpret_cast<uint32_t*>(oh + g0) = pack2h(oa[j][0] * inv0, oa[j][1] * inv0);
        *reinterpret_cast<uint32_t*>(oh + g1) = pack2h(oa[j][2] * inv1, oa[j][3] * inv1);
    }
}

// ---------------- layernorm (fp16 in -> fp16 out) -------------------------------
__global__ __launch_bounds__(256) void ln_h(const __half* __restrict__ in,
                                            const float* __restrict__ gamma,
                                            const float* __restrict__ beta,
                                            __half* __restrict__ outH)
{
    const int row = blockIdx.x, tid = threadIdx.x;
    size_t idx = (size_t)row * 1024 + tid * 4;
    uint2 raw = *reinterpret_cast<const uint2*>(in + idx);
    __half2 h01 = *reinterpret_cast<__half2*>(&raw.x);
    __half2 h23 = *reinterpret_cast<__half2*>(&raw.y);
    float4 v;
    v.x = __half2float(h01.x); v.y = __half2float(h01.y);
    v.z = __half2float(h23.x); v.w = __half2float(h23.y);
    float s  = v.x + v.y + v.z + v.w;
    float ss = v.x * v.x + v.y * v.y + v.z * v.z + v.w * v.w;
#pragma unroll
    for (int off = 16; off > 0; off >>= 1) {
        s  += __shfl_xor_sync(0xffffffffu, s,  off);
        ss += __shfl_xor_sync(0xffffffffu, ss, off);
    }
    __shared__ float sb[8], ssb[8];
    __shared__ float smu, sinv;
    if ((tid & 31) == 0) { sb[tid >> 5] = s; ssb[tid >> 5] = ss; }
    __syncthreads();
    if (tid == 0) {
        float S = 0.f, SS = 0.f;
#pragma unroll
        for (int i = 0; i < 8; i++) { S += sb[i]; SS += ssb[i]; }
        float mu  = S * (1.f / 1024.f);
        float var = SS * (1.f / 1024.f) - mu * mu;
        smu = mu; sinv = rsqrtf(var + 1e-5f);
    }
    __syncthreads();
    float mu = smu, inv = sinv;
    float4 g = *(const float4*)(gamma + tid * 4);
    float4 b = *(const float4*)(beta  + tid * 4);
    float o0 = (v.x - mu) * inv * g.x + b.x;
    float o1 = (v.y - mu) * inv * g.y + b.y;
    float o2 = (v.z - mu) * inv * g.z + b.z;
    float o3 = (v.w - mu) * inv * g.w + b.w;
    uint2 ow;
    ow.x = pack2h(o0, o1);
    ow.y = pack2h(o2, o3);
    *reinterpret_cast<uint2*>(outH + idx) = ow;
}

// ---------------- layernorm (fp32 in -> fp32 out) -------------------------------
__global__ __launch_bounds__(256) void ln_kernel(const float* __restrict__ in,
                                                 const float* __restrict__ gamma,
                                                 const float* __restrict__ beta,
                                                 float* __restrict__ outF)
{
    const int row = blockIdx.x, tid = threadIdx.x;
    const float* p = in + (size_t)row * 1024;
    float4 v = *(const float4*)(p + tid * 4);
    float s  = v.x + v.y + v.z + v.w;
    float ss = v.x * v.x + v.y * v.y + v.z * v.z + v.w * v.w;
#pragma unroll
    for (int off = 16; off > 0; off >>= 1) {
        s  += __shfl_xor_sync(0xffffffffu, s,  off);
        ss += __shfl_xor_sync(0xffffffffu, ss, off);
    }
    __shared__ float sb[8], ssb[8];
    __shared__ float smu, sinv;
    if ((tid & 31) == 0) { sb[tid >> 5] = s; ssb[tid >> 5] = ss; }
    __syncthreads();
    if (tid == 0) {
        float S = 0.f, SS = 0.f;
#pragma unroll
        for (int i = 0; i < 8; i++) { S += sb[i]; SS += ssb[i]; }
        float mu  = S * (1.f / 1024.f);
        float var = SS * (1.f / 1024.f) - mu * mu;
        smu = mu; sinv = rsqrtf(var + 1e-5f);
    }
    __syncthreads();
    float mu = smu, inv = sinv;
    float4 g = *(const float4*)(gamma + tid * 4);
    float4 b = *(const float4*)(beta  + tid * 4);
    float4 o;
    o.x = (v.x - mu) * inv * g.x + b.x;
    o.y = (v.y - mu) * inv * g.y + b.y;
    o.z = (v.z - mu) * inv * g.z + b.z;
    o.w = (v.w - mu) * inv * g.w + b.w;
    *(float4*)&outF[(size_t)row * 1024 + tid * 4] = o;
}

// ---------------- launch ----------------------------------------------------------
extern "C" void kernel_launch(void* const* d_in, const int* in_sizes, int n_in,
                              void* d_out, int out_size)
{
    const float* x     = (const float*)d_in[0];
    const float* Wq    = (const float*)d_in[1];
    const float* Wk    = (const float*)d_in[2];
    const float* Wv    = (const float*)d_in[3];
    const float* Wo    = (const float*)d_in[4];
    const float* ln1_g = (const float*)d_in[5];
    const float* ln1_b = (const float*)d_in[6];
    const float* W1    = (const float*)d_in[7];
    const float* b1    = (const float*)d_in[8];
    const float* W2    = (const float*)d_in[9];
    const float* b2    = (const float*)d_in[10];
    const float* ln2_g = (const float*)d_in[11];
    const float* ln2_b = (const float*)d_in[12];
    float* out = (float*)d_out;

    cudaFuncSetAttribute(gemm_mma,   cudaFuncAttributeMaxDynamicSharedMemorySize, GEMM_SMEM);
    cudaFuncSetAttribute(flash_hmma, cudaFuncAttributeMaxDynamicSharedMemorySize, ATT_SMEM);

    float *t2;
    __half *wqkvh, *xh, *qkvh, *oh, *woh, *t1h, *x1h, *w1h, *hh, *w2h;
    cudaGetSymbolAddress((void**)&t2,    g_t2);
    cudaGetSymbolAddress((void**)&wqkvh, g_wqkvh);
    cudaGetSymbolAddress((void**)&xh,    g_xh);
    cudaGetSymbolAddress((void**)&qkvh,  g_qkvh);
    cudaGetSymbolAddress((void**)&oh,    g_oh);
    cudaGetSymbolAddress((void**)&woh,   g_woh);
    cudaGetSymbolAddress((void**)&t1h,   g_t1h);
    cudaGetSymbolAddress((void**)&x1h,   g_x1h);
    cudaGetSymbolAddress((void**)&w1h,   g_w1h);
    cudaGetSymbolAddress((void**)&hh,    g_hh);
    cudaGetSymbolAddress((void**)&w2h,   g_w2h);

    // 0. critical-path prep only (wqkv pack + x convert)
    prep_small<<<8192, 256>>>(Wq, Wk, Wv, wqkvh, x, xh);

    // 1. QKV projection -> qkv fp16; z=1 plane converts Wo/W1/W2 in the tail
    gemm_mma<<<dim3(24, 32, 2), 128, GEMM_SMEM>>>(xh, wqkvh, 4096, 3072, 1024,
                                                  nullptr, nullptr, nullptr, 0, nullptr, qkvh,
                                                  Wo, woh, 64, W1, w1h, 256, W2, w2h, 256);
    // 2. flash attention -> o fp16 (64-row Q tiles, occ4)
    flash_hmma<<<dim3(32, NH, BATCH), 128, ATT_SMEM>>>(qkvh, oh);
    // 3. output projection + residual x -> t1 fp16
    gemm_mma<<<dim3(8, 32, 1), 128, GEMM_SMEM>>>(oh, woh, 4096, 1024, 1024,
                                                 nullptr, x, nullptr, 0, nullptr, t1h,
                                                 nullptr, nullptr, 0, nullptr, nullptr, 0,
                                                 nullptr, nullptr, 0);
    // 4. LN1 (fp16 in) -> x1 fp16
    ln_h<<<4096, 256>>>(t1h, ln1_g, ln1_b, x1h);
    // 5. FFN up + bias + relu -> h fp16
    gemm_mma<<<dim3(32, 32, 1), 128, GEMM_SMEM>>>(x1h, w1h, 4096, 4096, 1024,
                                                  b1, nullptr, nullptr, 1, nullptr, hh,
                                                  nullptr, nullptr, 0, nullptr, nullptr, 0,
                                                  nullptr, nullptr, 0);
    // 6. FFN down + bias + fp16 residual x1 -> t2 fp32
    gemm_mma<<<dim3(8, 32, 1), 128, GEMM_SMEM>>>(hh, w2h, 4096, 1024, 4096,
                                                 b2, nullptr, x1h, 0, t2, nullptr,
                                                 nullptr, nullptr, 0, nullptr, nullptr, 0,
                                                 nullptr, nullptr, 0);
    // 7. LN2 -> out
    ln_kernel<<<4096, 256>>>(t2, ln2_g, ln2_b, out);
}